// round 4
// baseline (speedup 1.0000x reference)
#include <cuda_runtime.h>
#include <cuda_bf16.h>
#include <cstdint>
#include <cstddef>

#define NTOK 16384
#define KDIM 2048
#define NDIM 1024

// ---------------- static scratch (no runtime allocation) --------------------
__device__ __align__(16) __nv_bfloat16 g_XH[(size_t)NTOK * KDIM];
__device__ __align__(16) __nv_bfloat16 g_XL[(size_t)NTOK * KDIM];
__device__ __align__(16) __nv_bfloat16 g_WH[(size_t)NDIM * KDIM]; // W^T hi [n][k]
__device__ __align__(16) __nv_bfloat16 g_WL[(size_t)NDIM * KDIM]; // W^T lo
__device__ __align__(16) float g_WIN[(size_t)NTOK * NDIM];
__device__ float    g_XSUM[KDIM];
__device__ float    g_COLSUM[NDIM];
__device__ float    g_V[NDIM];
__device__ float    g_U[KDIM];
__device__ float    g_SCORES[NTOK];
__device__ float    g_EXP[NTOK];
__device__ unsigned g_SMAXENC;
__device__ float    g_ZSUM;

// ---------------- helpers ----------------------------------------------------
__device__ __forceinline__ uint32_t smem_u32(const void* p) {
    uint32_t r;
    asm("{ .reg .u64 t; cvta.to.shared.u64 t, %1; cvt.u32.u64 %0, t; }"
        : "=r"(r) : "l"(p));
    return r;
}
__device__ __forceinline__ void cp16(uint32_t dst, const void* src) {
    asm volatile("cp.async.cg.shared.global [%0], [%1], 16;"
                 :: "r"(dst), "l"(src) : "memory");
}
__device__ __forceinline__ void ldsm4(uint32_t& r0, uint32_t& r1, uint32_t& r2,
                                      uint32_t& r3, uint32_t addr) {
    asm volatile("ldmatrix.sync.aligned.m8n8.x4.shared.b16 {%0,%1,%2,%3}, [%4];"
                 : "=r"(r0), "=r"(r1), "=r"(r2), "=r"(r3) : "r"(addr));
}
__device__ __forceinline__ void mma16816(float* c, const uint32_t* a,
                                         uint32_t b0, uint32_t b1) {
    asm volatile(
        "mma.sync.aligned.m16n8k16.row.col.f32.bf16.bf16.f32 "
        "{%0,%1,%2,%3}, {%4,%5,%6,%7}, {%8,%9}, {%0,%1,%2,%3};"
        : "+f"(c[0]), "+f"(c[1]), "+f"(c[2]), "+f"(c[3])
        : "r"(a[0]), "r"(a[1]), "r"(a[2]), "r"(a[3]), "r"(b0), "r"(b1));
}
__device__ __forceinline__ unsigned fenc(float f) {
    unsigned u = __float_as_uint(f);
    return (u & 0x80000000u) ? ~u : (u | 0x80000000u);
}
__device__ __forceinline__ float fdec(unsigned e) {
    unsigned u = (e & 0x80000000u) ? (e & 0x7fffffffu) : ~e;
    return __uint_as_float(u);
}
__device__ __forceinline__ void split_bf16(float x, __nv_bfloat16& h, __nv_bfloat16& l) {
    h = __float2bfloat16(x);
    l = __float2bfloat16(x - __bfloat162float(h));
}

// ---------------- small kernels ----------------------------------------------
__global__ void k_init() {
    int i = blockIdx.x * 1024 + threadIdx.x;
    if (i < KDIM) g_XSUM[i] = 0.f;
    if (i < NDIM) g_COLSUM[i] = 0.f;
    if (i == 0) { g_SMAXENC = 0x007FFFFFu; g_ZSUM = 0.f; } // enc(-inf)
}

__global__ void k_convX(const float* __restrict__ X) {
    size_t i4 = (size_t)blockIdx.x * blockDim.x + threadIdx.x;
    float4 x = reinterpret_cast<const float4*>(X)[i4];
    __nv_bfloat16 h0,l0,h1,l1,h2,l2,h3,l3;
    split_bf16(x.x,h0,l0); split_bf16(x.y,h1,l1);
    split_bf16(x.z,h2,l2); split_bf16(x.w,h3,l3);
    __nv_bfloat162* XH2 = reinterpret_cast<__nv_bfloat162*>(g_XH);
    __nv_bfloat162* XL2 = reinterpret_cast<__nv_bfloat162*>(g_XL);
    XH2[2*i4]   = __nv_bfloat162(h0,h1);
    XH2[2*i4+1] = __nv_bfloat162(h2,h3);
    XL2[2*i4]   = __nv_bfloat162(l0,l1);
    XL2[2*i4+1] = __nv_bfloat162(l2,l3);
}

__global__ void k_convW(const float* __restrict__ W) {
    __shared__ float t[32][33];
    int k0 = blockIdx.x * 32, n0 = blockIdx.y * 32;
    int tx = threadIdx.x, ty = threadIdx.y;       // (32, 8)
    #pragma unroll
    for (int i = ty; i < 32; i += 8)
        t[i][tx] = W[(size_t)(k0 + i) * NDIM + n0 + tx];
    __syncthreads();
    #pragma unroll
    for (int i = ty; i < 32; i += 8) {
        __nv_bfloat16 h, l;
        split_bf16(t[tx][i], h, l);               // = W[k0+tx][n0+i]
        g_WH[(size_t)(n0 + i) * KDIM + k0 + tx] = h;
        g_WL[(size_t)(n0 + i) * KDIM + k0 + tx] = l;
    }
}

// xsum[k] = sum_i X[i,k]
__global__ void k_xsum(const float* __restrict__ X) {
    int k = blockIdx.x * 256 + threadIdx.x;
    int r0 = blockIdx.y * 256;
    float acc = 0.f;
    for (int r = 0; r < 256; ++r)
        acc += X[(size_t)(r0 + r) * KDIM + k];
    atomicAdd(&g_XSUM[k], acc);
}

// colsum[n] += sum over k-chunk of xsum[k]*W[k][n]
__global__ void k_v(const float* __restrict__ W) {
    int n = blockIdx.x * 256 + threadIdx.x;
    int kb = blockIdx.y * 256;
    float acc = 0.f;
    for (int k = 0; k < 256; ++k)
        acc += g_XSUM[kb + k] * W[(size_t)(kb + k) * NDIM + n];
    atomicAdd(&g_COLSUM[n], acc);
}

__global__ void k_vfin(const float* __restrict__ a) {
    int n = blockIdx.x * 256 + threadIdx.x;
    g_V[n] = a[n] * g_COLSUM[n];
}

// u[k] = sum_n W[k][n]*v[n]
__global__ void k_u(const float* __restrict__ W) {
    __shared__ float sv[NDIM];
    int tid = threadIdx.x, wid = tid >> 5, lid = tid & 31;
    #pragma unroll
    for (int j = 0; j < 4; ++j) sv[tid + 256 * j] = g_V[tid + 256 * j];
    __syncthreads();
    int k = blockIdx.x * 8 + wid;
    float acc = 0.f;
    #pragma unroll 8
    for (int j = 0; j < 32; ++j)
        acc += W[(size_t)k * NDIM + lid + 32 * j] * sv[lid + 32 * j];
    #pragma unroll
    for (int o = 16; o > 0; o >>= 1) acc += __shfl_xor_sync(0xffffffff, acc, o);
    if (lid == 0) g_U[k] = acc;
}

// scores[i] = X[i,:] . u ; track max via encoded atomicMax
__global__ void k_scores(const float* __restrict__ X) {
    __shared__ float su[KDIM];
    int tid = threadIdx.x, wid = tid >> 5, lid = tid & 31;
    #pragma unroll
    for (int j = 0; j < 8; ++j) su[tid + 256 * j] = g_U[tid + 256 * j];
    __syncthreads();
    int i = blockIdx.x * 8 + wid;
    const float* xr = X + (size_t)i * KDIM;
    float acc = 0.f;
    #pragma unroll 8
    for (int j = 0; j < 64; ++j)
        acc += xr[lid + 32 * j] * su[lid + 32 * j];
    #pragma unroll
    for (int o = 16; o > 0; o >>= 1) acc += __shfl_xor_sync(0xffffffff, acc, o);
    if (lid == 0) {
        g_SCORES[i] = acc;
        atomicMax(&g_SMAXENC, fenc(acc));
    }
}

__global__ void k_exp() {
    __shared__ float red[256];
    int i = blockIdx.x * 256 + threadIdx.x;
    float smax = fdec(g_SMAXENC);
    float e = expf(g_SCORES[i] - smax);
    g_EXP[i] = e;
    red[threadIdx.x] = e;
    __syncthreads();
    for (int o = 128; o > 0; o >>= 1) {
        if (threadIdx.x < o) red[threadIdx.x] += red[threadIdx.x + o];
        __syncthreads();
    }
    if (threadIdx.x == 0) atomicAdd(&g_ZSUM, red[0]);
}

__global__ void k_out(float* __restrict__ out) {
    size_t i4 = (size_t)blockIdx.x * blockDim.x + threadIdx.x;
    int row = (int)(i4 >> 8);                 // 256 float4 per row
    float sc = g_EXP[row] / g_ZSUM;
    float4 w = reinterpret_cast<const float4*>(g_WIN)[i4];
    w.x *= sc; w.y *= sc; w.z *= sc; w.w *= sc;
    reinterpret_cast<float4*>(out)[i4] = w;
}

// ---------------- GEMM: g_WIN = X @ W via mma.sync bf16x3 --------------------
// BM=128, BN=256, BK=32; 256 threads (8 warps, 2x4, 64x64 warp tile);
// 3-stage cp.async pipeline; 80B padded smem rows (conflict-free ldmatrix).
#define BM 128
#define BN 256
#define BK 32
#define ROWB 80
#define SA_SZ (2 * BM * ROWB)            // 20480 (hi, lo)
#define SB_SZ (2 * BN * ROWB)            // 40960
#define STG_SZ (SA_SZ + SB_SZ)           // 61440
#define NSTAGE 3
#define GEMM_SMEM (NSTAGE * STG_SZ)      // 184320

__device__ __forceinline__ void load_chunk(uint32_t stb, int m0, int n0, int kc, int tid) {
    const size_t rowb = KDIM * 2;
    size_t ck = (size_t)kc * 64;          // 32 bf16 = 64 bytes along K
    // A: 2 mats x 128 rows x 4 x 16B = 1024 slots
    #pragma unroll
    for (int it = 0; it < 4; ++it) {
        int idx = tid + it * 256;
        int mat = idx >> 9, rem = idx & 511;
        int row = rem >> 2, c = rem & 3;
        const char* src = (const char*)(mat ? g_XL : g_XH)
                        + (size_t)(m0 + row) * rowb + ck + c * 16;
        cp16(stb + mat * (BM * ROWB) + row * ROWB + c * 16, src);
    }
    // B: 2 mats x 256 rows x 4 x 16B = 2048 slots
    #pragma unroll
    for (int it = 0; it < 8; ++it) {
        int idx = tid + it * 256;
        int mat = idx >> 10, rem = idx & 1023;
        int row = rem >> 2, c = rem & 3;
        const char* src = (const char*)(mat ? g_WL : g_WH)
                        + (size_t)(n0 + row) * rowb + ck + c * 16;
        cp16(stb + SA_SZ + mat * (BN * ROWB) + row * ROWB + c * 16, src);
    }
    asm volatile("cp.async.commit_group;" ::: "memory");
}

__global__ void __launch_bounds__(256, 1) k_gemm() {
    extern __shared__ char smem[];
    uint32_t sb = smem_u32(smem);
    const int tid  = threadIdx.x;
    const int wid  = tid >> 5, lane = tid & 31;
    const int n0   = blockIdx.x * BN;     // n fastest: A-panel sharers co-wave
    const int m0   = blockIdx.y * BM;
    const int m_w  = (wid & 1) * 64;
    const int n_w  = (wid >> 1) * 64;

    float C[4][8][4];
    #pragma unroll
    for (int i = 0; i < 4; ++i)
        #pragma unroll
        for (int j = 0; j < 8; ++j)
            #pragma unroll
            for (int q = 0; q < 4; ++q) C[i][j][q] = 0.f;

    // ldmatrix lane address components
    const int a_row = m_w + (lane & 15);
    const int a_cb  = (lane >> 4) * 16;
    const int b_sub = lane >> 3;
    const int b_row = n_w + (lane & 7) + ((b_sub >> 1) << 3);
    const int b_cb  = (b_sub & 1) * 16;

    load_chunk(sb, m0, n0, 0, tid);
    load_chunk(sb + STG_SZ, m0, n0, 1, tid);

    const int NCH = KDIM / BK;            // 64
    for (int kc = 0; kc < NCH; ++kc) {
        if (kc == NCH - 1) asm volatile("cp.async.wait_group 0;" ::: "memory");
        else               asm volatile("cp.async.wait_group 1;" ::: "memory");
        __syncthreads();
        uint32_t stb = sb + (kc % NSTAGE) * STG_SZ;
        if (kc + 2 < NCH)
            load_chunk(sb + ((kc + 2) % NSTAGE) * STG_SZ, m0, n0, kc + 2, tid);

        #pragma unroll
        for (int ks = 0; ks < 2; ++ks) {
            uint32_t AH[4][4], AL[4][4], BHg[4][4], BLg[4][4];
            uint32_t aH = stb + a_row * ROWB + ks * 32 + a_cb;
            uint32_t aL = aH + BM * ROWB;
            #pragma unroll
            for (int mg = 0; mg < 4; ++mg) {
                ldsm4(AH[mg][0], AH[mg][1], AH[mg][2], AH[mg][3], aH + mg * 16 * ROWB);
                ldsm4(AL[mg][0], AL[mg][1], AL[mg][2], AL[mg][3], aL + mg * 16 * ROWB);
            }
            uint32_t bH = stb + SA_SZ + b_row * ROWB + ks * 32 + b_cb;
            uint32_t bL = bH + BN * ROWB;
            #pragma unroll
            for (int ng = 0; ng < 4; ++ng) {
                ldsm4(BHg[ng][0], BHg[ng][1], BHg[ng][2], BHg[ng][3], bH + ng * 16 * ROWB);
                ldsm4(BLg[ng][0], BLg[ng][1], BLg[ng][2], BLg[ng][3], bL + ng * 16 * ROWB);
            }
            #pragma unroll
            for (int mg = 0; mg < 4; ++mg)
                #pragma unroll
                for (int ng = 0; ng < 4; ++ng) {
                    mma16816(C[mg][2*ng],   AH[mg], BHg[ng][0], BHg[ng][1]);
                    mma16816(C[mg][2*ng+1], AH[mg], BHg[ng][2], BHg[ng][3]);
                    mma16816(C[mg][2*ng],   AL[mg], BHg[ng][0], BHg[ng][1]);
                    mma16816(C[mg][2*ng+1], AL[mg], BHg[ng][2], BHg[ng][3]);
                    mma16816(C[mg][2*ng],   AH[mg], BLg[ng][0], BLg[ng][1]);
                    mma16816(C[mg][2*ng+1], AH[mg], BLg[ng][2], BLg[ng][3]);
                }
        }
    }

    // epilogue: C[mg][ng8] frag -> g_WIN
    #pragma unroll
    for (int mg = 0; mg < 4; ++mg) {
        int r0 = m0 + m_w + 16 * mg + (lane >> 2);
        #pragma unroll
        for (int ng8 = 0; ng8 < 8; ++ng8) {
            int col = n0 + n_w + 8 * ng8 + 2 * (lane & 3);
            float2* p0 = (float2*)&g_WIN[(size_t)r0 * NDIM + col];
            float2* p1 = (float2*)&g_WIN[(size_t)(r0 + 8) * NDIM + col];
            *p0 = make_float2(C[mg][ng8][0], C[mg][ng8][1]);
            *p1 = make_float2(C[mg][ng8][2], C[mg][ng8][3]);
        }
    }
}

// ---------------- launch ------------------------------------------------------
extern "C" void kernel_launch(void* const* d_in, const int* in_sizes, int n_in,
                              void* d_out, int out_size) {
    // bind inputs by element count (robust to metadata ordering)
    const float* X = nullptr; const float* W = nullptr; const float* a = nullptr;
    for (int i = 0; i < n_in; ++i) {
        if (in_sizes[i] == NTOK * KDIM)      X = (const float*)d_in[i];
        else if (in_sizes[i] == KDIM * NDIM) W = (const float*)d_in[i];
        else if (in_sizes[i] == NDIM)        a = (const float*)d_in[i];
    }
    float* out = (float*)d_out;

    cudaFuncSetAttribute(k_gemm, cudaFuncAttributeMaxDynamicSharedMemorySize,
                         GEMM_SMEM);

    k_init<<<2, 1024>>>();
    k_convX<<<(NTOK * (KDIM / 4)) / 256, 256>>>(X);
    k_convW<<<dim3(KDIM / 32, NDIM / 32), dim3(32, 8)>>>(W);
    k_xsum<<<dim3(KDIM / 256, NTOK / 256), 256>>>(X);
    k_v<<<dim3(NDIM / 256, KDIM / 256), 256>>>(W);
    k_vfin<<<NDIM / 256, 256>>>(a);
    k_u<<<KDIM / 8, 256>>>(W);
    k_gemm<<<dim3(NDIM / BN, NTOK / BM), 256, GEMM_SMEM>>>();
    k_scores<<<NTOK / 8, 256>>>(X);
    k_exp<<<NTOK / 256, 256>>>();
    k_out<<<(NTOK * (NDIM / 4)) / 256, 256>>>(out);
}

// round 5
// speedup vs baseline: 1.0503x; 1.0503x over previous
#include <cuda_runtime.h>
#include <cuda_bf16.h>
#include <cstdint>
#include <cstddef>

#define NTOK 16384
#define KDIM 2048
#define NDIM 1024

// ---------------- static scratch (no runtime allocation) --------------------
__device__ __align__(16) __nv_bfloat16 g_XH[(size_t)NTOK * KDIM];
__device__ __align__(16) __nv_bfloat16 g_XL[(size_t)NTOK * KDIM];
__device__ __align__(16) __nv_bfloat16 g_WH[(size_t)NDIM * KDIM]; // W^T hi [n][k]
__device__ __align__(16) __nv_bfloat16 g_WL[(size_t)NDIM * KDIM]; // W^T lo
__device__ float    g_XSUM[KDIM];
__device__ float    g_COLSUM[NDIM];
__device__ float    g_V[NDIM];
__device__ float    g_U[KDIM];
__device__ float    g_SCORES[NTOK];
__device__ float    g_EXP[NTOK];
__device__ unsigned g_SMAXENC;
__device__ float    g_ZSUM;

// ---------------- helpers ----------------------------------------------------
__device__ __forceinline__ uint32_t smem_u32(const void* p) {
    uint32_t r;
    asm("{ .reg .u64 t; cvta.to.shared.u64 t, %1; cvt.u32.u64 %0, t; }"
        : "=r"(r) : "l"(p));
    return r;
}
__device__ __forceinline__ void cp16(uint32_t dst, const void* src) {
    asm volatile("cp.async.cg.shared.global [%0], [%1], 16;"
                 :: "r"(dst), "l"(src) : "memory");
}
__device__ __forceinline__ void ldsm4(uint32_t& r0, uint32_t& r1, uint32_t& r2,
                                      uint32_t& r3, uint32_t addr) {
    asm volatile("ldmatrix.sync.aligned.m8n8.x4.shared.b16 {%0,%1,%2,%3}, [%4];"
                 : "=r"(r0), "=r"(r1), "=r"(r2), "=r"(r3) : "r"(addr));
}
__device__ __forceinline__ void mma16816(float* c, const uint32_t* a,
                                         uint32_t b0, uint32_t b1) {
    asm volatile(
        "mma.sync.aligned.m16n8k16.row.col.f32.bf16.bf16.f32 "
        "{%0,%1,%2,%3}, {%4,%5,%6,%7}, {%8,%9}, {%0,%1,%2,%3};"
        : "+f"(c[0]), "+f"(c[1]), "+f"(c[2]), "+f"(c[3])
        : "r"(a[0]), "r"(a[1]), "r"(a[2]), "r"(a[3]), "r"(b0), "r"(b1));
}
__device__ __forceinline__ unsigned fenc(float f) {
    unsigned u = __float_as_uint(f);
    return (u & 0x80000000u) ? ~u : (u | 0x80000000u);
}
__device__ __forceinline__ float fdec(unsigned e) {
    unsigned u = (e & 0x80000000u) ? (e & 0x7fffffffu) : ~e;
    return __uint_as_float(u);
}
__device__ __forceinline__ void split_bf16(float x, __nv_bfloat16& h, __nv_bfloat16& l) {
    h = __float2bfloat16(x);
    l = __float2bfloat16(x - __bfloat162float(h));
}

// ---------------- small kernels ----------------------------------------------
__global__ void k_init() {
    int i = blockIdx.x * 1024 + threadIdx.x;
    if (i < KDIM) g_XSUM[i] = 0.f;
    if (i < NDIM) g_COLSUM[i] = 0.f;
    if (i == 0) { g_SMAXENC = 0x007FFFFFu; g_ZSUM = 0.f; } // enc(-inf)
}

__global__ void k_convX(const float* __restrict__ X) {
    size_t i4 = (size_t)blockIdx.x * blockDim.x + threadIdx.x;
    float4 x = reinterpret_cast<const float4*>(X)[i4];
    __nv_bfloat16 h0,l0,h1,l1,h2,l2,h3,l3;
    split_bf16(x.x,h0,l0); split_bf16(x.y,h1,l1);
    split_bf16(x.z,h2,l2); split_bf16(x.w,h3,l3);
    __nv_bfloat162* XH2 = reinterpret_cast<__nv_bfloat162*>(g_XH);
    __nv_bfloat162* XL2 = reinterpret_cast<__nv_bfloat162*>(g_XL);
    XH2[2*i4]   = __nv_bfloat162(h0,h1);
    XH2[2*i4+1] = __nv_bfloat162(h2,h3);
    XL2[2*i4]   = __nv_bfloat162(l0,l1);
    XL2[2*i4+1] = __nv_bfloat162(l2,l3);
}

__global__ void k_convW(const float* __restrict__ W) {
    __shared__ float t[32][33];
    int k0 = blockIdx.x * 32, n0 = blockIdx.y * 32;
    int tx = threadIdx.x, ty = threadIdx.y;       // (32, 8)
    #pragma unroll
    for (int i = ty; i < 32; i += 8)
        t[i][tx] = W[(size_t)(k0 + i) * NDIM + n0 + tx];
    __syncthreads();
    #pragma unroll
    for (int i = ty; i < 32; i += 8) {
        __nv_bfloat16 h, l;
        split_bf16(t[tx][i], h, l);               // = W[k0+tx][n0+i]
        g_WH[(size_t)(n0 + i) * KDIM + k0 + tx] = h;
        g_WL[(size_t)(n0 + i) * KDIM + k0 + tx] = l;
    }
}

// xsum[k] = sum_i X[i,k]
__global__ void k_xsum(const float* __restrict__ X) {
    int k = blockIdx.x * 256 + threadIdx.x;
    int r0 = blockIdx.y * 128;
    float a0 = 0.f, a1 = 0.f;
    #pragma unroll 4
    for (int r = 0; r < 128; r += 2) {
        a0 += X[(size_t)(r0 + r) * KDIM + k];
        a1 += X[(size_t)(r0 + r + 1) * KDIM + k];
    }
    atomicAdd(&g_XSUM[k], a0 + a1);
}

// colsum[n] += sum over k-chunk of xsum[k]*W[k][n]
__global__ void k_v(const float* __restrict__ W) {
    int n = blockIdx.x * 256 + threadIdx.x;
    int kb = blockIdx.y * 256;
    float acc = 0.f;
    for (int k = 0; k < 256; ++k)
        acc += g_XSUM[kb + k] * W[(size_t)(kb + k) * NDIM + n];
    atomicAdd(&g_COLSUM[n], acc);
}

__global__ void k_vfin(const float* __restrict__ a) {
    int n = blockIdx.x * 256 + threadIdx.x;
    g_V[n] = a[n] * g_COLSUM[n];
}

// u[k] = sum_n W[k][n]*v[n]
__global__ void k_u(const float* __restrict__ W) {
    __shared__ float sv[NDIM];
    int tid = threadIdx.x, wid = tid >> 5, lid = tid & 31;
    #pragma unroll
    for (int j = 0; j < 4; ++j) sv[tid + 256 * j] = g_V[tid + 256 * j];
    __syncthreads();
    int k = blockIdx.x * 8 + wid;
    float acc = 0.f;
    #pragma unroll 8
    for (int j = 0; j < 32; ++j)
        acc += W[(size_t)k * NDIM + lid + 32 * j] * sv[lid + 32 * j];
    #pragma unroll
    for (int o = 16; o > 0; o >>= 1) acc += __shfl_xor_sync(0xffffffff, acc, o);
    if (lid == 0) g_U[k] = acc;
}

// scores[i] = X[i,:] . u ; track max via encoded atomicMax
__global__ void k_scores(const float* __restrict__ X) {
    __shared__ float su[KDIM];
    int tid = threadIdx.x, wid = tid >> 5, lid = tid & 31;
    #pragma unroll
    for (int j = 0; j < 8; ++j) su[tid + 256 * j] = g_U[tid + 256 * j];
    __syncthreads();
    int i = blockIdx.x * 8 + wid;
    const float* xr = X + (size_t)i * KDIM;
    float acc = 0.f;
    #pragma unroll 8
    for (int j = 0; j < 64; ++j)
        acc += xr[lid + 32 * j] * su[lid + 32 * j];
    #pragma unroll
    for (int o = 16; o > 0; o >>= 1) acc += __shfl_xor_sync(0xffffffff, acc, o);
    if (lid == 0) {
        g_SCORES[i] = acc;
        atomicMax(&g_SMAXENC, fenc(acc));
    }
}

__global__ void k_exp() {
    __shared__ float red[256];
    int i = blockIdx.x * 256 + threadIdx.x;
    float smax = fdec(g_SMAXENC);
    float e = expf(g_SCORES[i] - smax);
    g_EXP[i] = e;
    red[threadIdx.x] = e;
    __syncthreads();
    for (int o = 128; o > 0; o >>= 1) {
        if (threadIdx.x < o) red[threadIdx.x] += red[threadIdx.x + o];
        __syncthreads();
    }
    if (threadIdx.x == 0) atomicAdd(&g_ZSUM, red[0]);
}

// ---------------- GEMM: out = (X @ W) * attn  via mma.sync bf16x3 ------------
// BM=128, BN=256, BK=32; 512 threads (16 warps, 2x8, 64x32 warp tile);
// 3-stage cp.async pipeline; 80B padded smem rows (conflict-free ldmatrix);
// fused softmax-scaled epilogue (no w_input round-trip).
#define BM 128
#define BN 256
#define BK 32
#define ROWB 80
#define SA_SZ (2 * BM * ROWB)            // 20480 (hi, lo)
#define SB_SZ (2 * BN * ROWB)            // 40960
#define STG_SZ (SA_SZ + SB_SZ)           // 61440
#define NSTAGE 3
#define GEMM_SMEM (NSTAGE * STG_SZ)      // 184320
#define GTHREADS 512

__device__ __forceinline__ void load_chunk(uint32_t stb, int m0, int n0, int kc, int tid) {
    const size_t rowb = KDIM * 2;
    size_t ck = (size_t)kc * 64;          // 32 bf16 = 64 bytes along K
    // A: 2 mats x 128 rows x 4 x 16B = 1024 slots
    #pragma unroll
    for (int it = 0; it < 2; ++it) {
        int idx = tid + it * GTHREADS;
        int mat = idx >> 9, rem = idx & 511;
        int row = rem >> 2, c = rem & 3;
        const char* src = (const char*)(mat ? g_XL : g_XH)
                        + (size_t)(m0 + row) * rowb + ck + c * 16;
        cp16(stb + mat * (BM * ROWB) + row * ROWB + c * 16, src);
    }
    // B: 2 mats x 256 rows x 4 x 16B = 2048 slots
    #pragma unroll
    for (int it = 0; it < 4; ++it) {
        int idx = tid + it * GTHREADS;
        int mat = idx >> 10, rem = idx & 1023;
        int row = rem >> 2, c = rem & 3;
        const char* src = (const char*)(mat ? g_WL : g_WH)
                        + (size_t)(n0 + row) * rowb + ck + c * 16;
        cp16(stb + SA_SZ + mat * (BN * ROWB) + row * ROWB + c * 16, src);
    }
    asm volatile("cp.async.commit_group;" ::: "memory");
}

__global__ void __launch_bounds__(GTHREADS, 1) k_gemm(float* __restrict__ out) {
    extern __shared__ char smem[];
    uint32_t sb = smem_u32(smem);
    const int tid  = threadIdx.x;
    const int wid  = tid >> 5, lane = tid & 31;
    const int n0   = blockIdx.x * BN;     // n fastest: A-panel sharers co-wave
    const int m0   = blockIdx.y * BM;
    const int m_w  = (wid & 1) * 64;      // 2 warps over M
    const int n_w  = (wid >> 1) * 32;     // 8 warps over N

    float C[4][4][4];
    #pragma unroll
    for (int i = 0; i < 4; ++i)
        #pragma unroll
        for (int j = 0; j < 4; ++j)
            #pragma unroll
            for (int q = 0; q < 4; ++q) C[i][j][q] = 0.f;

    // ldmatrix lane address components (layout validated in R4 pass)
    const int a_row = m_w + (lane & 15);
    const int a_cb  = (lane >> 4) * 16;
    const int b_sub = lane >> 3;
    const int b_row = n_w + (lane & 7) + ((b_sub >> 1) << 3);
    const int b_cb  = (b_sub & 1) * 16;

    load_chunk(sb, m0, n0, 0, tid);
    load_chunk(sb + STG_SZ, m0, n0, 1, tid);

    const int NCH = KDIM / BK;            // 64
    for (int kc = 0; kc < NCH; ++kc) {
        if (kc == NCH - 1) asm volatile("cp.async.wait_group 0;" ::: "memory");
        else               asm volatile("cp.async.wait_group 1;" ::: "memory");
        __syncthreads();
        uint32_t stb = sb + (kc % NSTAGE) * STG_SZ;
        if (kc + 2 < NCH)
            load_chunk(sb + ((kc + 2) % NSTAGE) * STG_SZ, m0, n0, kc + 2, tid);

        #pragma unroll
        for (int ks = 0; ks < 2; ++ks) {
            uint32_t AH[4][4], AL[4][4];
            uint32_t aH = stb + a_row * ROWB + ks * 32 + a_cb;
            uint32_t aL = aH + BM * ROWB;
            #pragma unroll
            for (int mg = 0; mg < 4; ++mg) {
                ldsm4(AH[mg][0], AH[mg][1], AH[mg][2], AH[mg][3], aH + mg * 16 * ROWB);
                ldsm4(AL[mg][0], AL[mg][1], AL[mg][2], AL[mg][3], aL + mg * 16 * ROWB);
            }
            uint32_t bH = stb + SA_SZ + b_row * ROWB + ks * 32 + b_cb;
            uint32_t bL = bH + BN * ROWB;
            #pragma unroll
            for (int g = 0; g < 2; ++g) {
                uint32_t BH[4], BL[4];
                ldsm4(BH[0], BH[1], BH[2], BH[3], bH + g * 16 * ROWB);
                ldsm4(BL[0], BL[1], BL[2], BL[3], bL + g * 16 * ROWB);
                #pragma unroll
                for (int mg = 0; mg < 4; ++mg) {
                    mma16816(C[mg][2*g],   AH[mg], BH[0], BH[1]);
                    mma16816(C[mg][2*g+1], AH[mg], BH[2], BH[3]);
                    mma16816(C[mg][2*g],   AL[mg], BH[0], BH[1]);
                    mma16816(C[mg][2*g+1], AL[mg], BH[2], BH[3]);
                    mma16816(C[mg][2*g],   AH[mg], BL[0], BL[1]);
                    mma16816(C[mg][2*g+1], AH[mg], BL[2], BL[3]);
                }
            }
        }
    }

    // fused epilogue: out[r, c] = w_input[r, c] * exp[r] / zsum
    float inv = 1.f / g_ZSUM;
    #pragma unroll
    for (int mg = 0; mg < 4; ++mg) {
        int r0 = m0 + m_w + 16 * mg + (lane >> 2);
        float s0 = g_EXP[r0] * inv;
        float s1 = g_EXP[r0 + 8] * inv;
        #pragma unroll
        for (int g8 = 0; g8 < 4; ++g8) {
            int col = n0 + n_w + 8 * g8 + 2 * (lane & 3);
            float2* p0 = (float2*)&out[(size_t)r0 * NDIM + col];
            float2* p1 = (float2*)&out[(size_t)(r0 + 8) * NDIM + col];
            *p0 = make_float2(C[mg][g8][0] * s0, C[mg][g8][1] * s0);
            *p1 = make_float2(C[mg][g8][2] * s1, C[mg][g8][3] * s1);
        }
    }
}

// ---------------- launch ------------------------------------------------------
extern "C" void kernel_launch(void* const* d_in, const int* in_sizes, int n_in,
                              void* d_out, int out_size) {
    // bind inputs by element count (robust to metadata ordering)
    const float* X = nullptr; const float* W = nullptr; const float* a = nullptr;
    for (int i = 0; i < n_in; ++i) {
        if (in_sizes[i] == NTOK * KDIM)      X = (const float*)d_in[i];
        else if (in_sizes[i] == KDIM * NDIM) W = (const float*)d_in[i];
        else if (in_sizes[i] == NDIM)        a = (const float*)d_in[i];
    }
    float* out = (float*)d_out;

    cudaFuncSetAttribute(k_gemm, cudaFuncAttributeMaxDynamicSharedMemorySize,
                         GEMM_SMEM);

    k_init<<<2, 1024>>>();
    k_convX<<<(NTOK * (KDIM / 4)) / 256, 256>>>(X);
    k_convW<<<dim3(KDIM / 32, NDIM / 32), dim3(32, 8)>>>(W);
    k_xsum<<<dim3(KDIM / 256, NTOK / 128), 256>>>(X);
    k_v<<<dim3(NDIM / 256, KDIM / 256), 256>>>(W);
    k_vfin<<<NDIM / 256, 256>>>(a);
    k_u<<<KDIM / 8, 256>>>(W);
    k_scores<<<NTOK / 8, 256>>>(X);
    k_exp<<<NTOK / 256, 256>>>();
    k_gemm<<<dim3(NDIM / BN, NTOK / BM), GTHREADS, GEMM_SMEM>>>(out);
}

// round 7
// speedup vs baseline: 1.9240x; 1.8318x over previous
#include <cuda_runtime.h>
#include <cuda_fp16.h>
#include <cstdint>
#include <cstddef>

#define NTOK 16384
#define KDIM 2048
#define NDIM 1024

// ---------------- static scratch (no runtime allocation) --------------------
__device__ __align__(16) __half g_XH[(size_t)NTOK * KDIM];   // fp16(X)
__device__ __align__(16) __half g_WH[(size_t)NDIM * KDIM];   // fp16(W^T) [n][k]
__device__ float    g_XSUM[KDIM];
__device__ float    g_COLSUM[NDIM];
__device__ float    g_V[NDIM];
__device__ float    g_U[KDIM];
__device__ float    g_SCORES[NTOK];
__device__ float    g_EXP[NTOK];
__device__ unsigned g_SMAXENC;
__device__ float    g_ZSUM;

// ---------------- helpers ----------------------------------------------------
__device__ __forceinline__ uint32_t smem_u32(const void* p) {
    uint32_t r;
    asm("{ .reg .u64 t; cvta.to.shared.u64 t, %1; cvt.u32.u64 %0, t; }"
        : "=r"(r) : "l"(p));
    return r;
}
__device__ __forceinline__ void cp16(uint32_t dst, const void* src) {
    asm volatile("cp.async.cg.shared.global [%0], [%1], 16;"
                 :: "r"(dst), "l"(src) : "memory");
}
__device__ __forceinline__ void ldsm4(uint32_t& r0, uint32_t& r1, uint32_t& r2,
                                      uint32_t& r3, uint32_t addr) {
    asm volatile("ldmatrix.sync.aligned.m8n8.x4.shared.b16 {%0,%1,%2,%3}, [%4];"
                 : "=r"(r0), "=r"(r1), "=r"(r2), "=r"(r3) : "r"(addr));
}
__device__ __forceinline__ void mma16816(float* c, const uint32_t* a,
                                         uint32_t b0, uint32_t b1) {
    asm volatile(
        "mma.sync.aligned.m16n8k16.row.col.f32.f16.f16.f32 "
        "{%0,%1,%2,%3}, {%4,%5,%6,%7}, {%8,%9}, {%0,%1,%2,%3};"
        : "+f"(c[0]), "+f"(c[1]), "+f"(c[2]), "+f"(c[3])
        : "r"(a[0]), "r"(a[1]), "r"(a[2]), "r"(a[3]), "r"(b0), "r"(b1));
}
__device__ __forceinline__ unsigned fenc(float f) {
    unsigned u = __float_as_uint(f);
    return (u & 0x80000000u) ? ~u : (u | 0x80000000u);
}
__device__ __forceinline__ float fdec(unsigned e) {
    unsigned u = (e & 0x80000000u) ? (e & 0x7fffffffu) : ~e;
    return __uint_as_float(u);
}

// ---------------- small kernels ----------------------------------------------
__global__ void k_init() {
    int i = blockIdx.x * 1024 + threadIdx.x;
    if (i < KDIM) g_XSUM[i] = 0.f;
    if (i < NDIM) g_COLSUM[i] = 0.f;
    if (i == 0) { g_SMAXENC = 0x007FFFFFu; g_ZSUM = 0.f; } // enc(-inf)
}

__global__ void k_convX(const float* __restrict__ X) {
    size_t i4 = (size_t)blockIdx.x * blockDim.x + threadIdx.x;
    float4 x = reinterpret_cast<const float4*>(X)[i4];
    __half2* XH2 = reinterpret_cast<__half2*>(g_XH);
    XH2[2*i4]   = __floats2half2_rn(x.x, x.y);
    XH2[2*i4+1] = __floats2half2_rn(x.z, x.w);
}

__global__ void k_convW(const float* __restrict__ W) {
    __shared__ float t[32][33];
    int k0 = blockIdx.x * 32, n0 = blockIdx.y * 32;
    int tx = threadIdx.x, ty = threadIdx.y;       // (32, 8)
    #pragma unroll
    for (int i = ty; i < 32; i += 8)
        t[i][tx] = W[(size_t)(k0 + i) * NDIM + n0 + tx];
    __syncthreads();
    #pragma unroll
    for (int i = ty; i < 32; i += 8)
        g_WH[(size_t)(n0 + i) * KDIM + k0 + tx] = __float2half_rn(t[tx][i]);
}

// xsum[k] = sum_i X[i,k]
__global__ void k_xsum(const float* __restrict__ X) {
    int k = blockIdx.x * 256 + threadIdx.x;
    int r0 = blockIdx.y * 128;
    float a0 = 0.f, a1 = 0.f;
    #pragma unroll 4
    for (int r = 0; r < 128; r += 2) {
        a0 += X[(size_t)(r0 + r) * KDIM + k];
        a1 += X[(size_t)(r0 + r + 1) * KDIM + k];
    }
    atomicAdd(&g_XSUM[k], a0 + a1);
}

// colsum[n] += sum over k-chunk of xsum[k]*W[k][n]
__global__ void k_v(const float* __restrict__ W) {
    int n = blockIdx.x * 256 + threadIdx.x;
    int kb = blockIdx.y * 256;
    float acc = 0.f;
    for (int k = 0; k < 256; ++k)
        acc += g_XSUM[kb + k] * W[(size_t)(kb + k) * NDIM + n];
    atomicAdd(&g_COLSUM[n], acc);
}

__global__ void k_vfin(const float* __restrict__ a) {
    int n = blockIdx.x * 256 + threadIdx.x;
    g_V[n] = a[n] * g_COLSUM[n];
}

// u[k] = sum_n W[k][n]*v[n]
__global__ void k_u(const float* __restrict__ W) {
    __shared__ float sv[NDIM];
    int tid = threadIdx.x, wid = tid >> 5, lid = tid & 31;
    #pragma unroll
    for (int j = 0; j < 4; ++j) sv[tid + 256 * j] = g_V[tid + 256 * j];
    __syncthreads();
    int k = blockIdx.x * 8 + wid;
    float acc = 0.f;
    #pragma unroll 8
    for (int j = 0; j < 32; ++j)
        acc += W[(size_t)k * NDIM + lid + 32 * j] * sv[lid + 32 * j];
    #pragma unroll
    for (int o = 16; o > 0; o >>= 1) acc += __shfl_xor_sync(0xffffffff, acc, o);
    if (lid == 0) g_U[k] = acc;
}

// scores[i] = X[i,:] . u ; track max via encoded atomicMax
__global__ void k_scores(const float* __restrict__ X) {
    __shared__ float su[KDIM];
    int tid = threadIdx.x, wid = tid >> 5, lid = tid & 31;
    #pragma unroll
    for (int j = 0; j < 8; ++j) su[tid + 256 * j] = g_U[tid + 256 * j];
    __syncthreads();
    int i = blockIdx.x * 8 + wid;
    const float* xr = X + (size_t)i * KDIM;
    float acc = 0.f;
    #pragma unroll 8
    for (int j = 0; j < 64; ++j)
        acc += xr[lid + 32 * j] * su[lid + 32 * j];
    #pragma unroll
    for (int o = 16; o > 0; o >>= 1) acc += __shfl_xor_sync(0xffffffff, acc, o);
    if (lid == 0) {
        g_SCORES[i] = acc;
        atomicMax(&g_SMAXENC, fenc(acc));
    }
}

__global__ void k_exp() {
    __shared__ float red[256];
    int i = blockIdx.x * 256 + threadIdx.x;
    float smax = fdec(g_SMAXENC);
    float e = expf(g_SCORES[i] - smax);
    g_EXP[i] = e;
    red[threadIdx.x] = e;
    __syncthreads();
    for (int o = 128; o > 0; o >>= 1) {
        if (threadIdx.x < o) red[threadIdx.x] += red[threadIdx.x + o];
        __syncthreads();
    }
    if (threadIdx.x == 0) atomicAdd(&g_ZSUM, red[0]);
}

// ---------------- GEMM: out = (X @ W) * attn  via mma.sync fp16 --------------
// BM=128, BN=256, BK=32; 512 threads (16 warps, 2x8, 64x32 warp tile);
// 3-stage cp.async pipeline; 80B padded smem rows (conflict-free ldmatrix);
// fused softmax-scaled epilogue. Single fp16 pass (fp32 accumulate).
#define BM 128
#define BN 256
#define BK 32
#define ROWB 80
#define SA_SZ (BM * ROWB)                // 10240
#define SB_SZ (BN * ROWB)                // 20480
#define STG_SZ (SA_SZ + SB_SZ)           // 30720
#define NSTAGE 3
#define GEMM_SMEM (NSTAGE * STG_SZ)      // 92160
#define GTHREADS 512

__device__ __forceinline__ void load_chunk(uint32_t stb, int m0, int n0, int kc, int tid) {
    const size_t rowb = KDIM * 2;
    size_t ck = (size_t)kc * 64;          // 32 fp16 = 64 bytes along K
    // A: 128 rows x 4 x 16B = 512 slots
    {
        int row = tid >> 2, c = tid & 3;
        const char* src = (const char*)g_XH + (size_t)(m0 + row) * rowb + ck + c * 16;
        cp16(stb + row * ROWB + c * 16, src);
    }
    // B: 256 rows x 4 x 16B = 1024 slots
    #pragma unroll
    for (int it = 0; it < 2; ++it) {
        int idx = tid + it * GTHREADS;
        int row = idx >> 2, c = idx & 3;
        const char* src = (const char*)g_WH + (size_t)(n0 + row) * rowb + ck + c * 16;
        cp16(stb + SA_SZ + row * ROWB + c * 16, src);
    }
    asm volatile("cp.async.commit_group;" ::: "memory");
}

__global__ void __launch_bounds__(GTHREADS, 1) k_gemm(float* __restrict__ out) {
    extern __shared__ char smem[];
    uint32_t sb = smem_u32(smem);
    const int tid  = threadIdx.x;
    const int wid  = tid >> 5, lane = tid & 31;
    const int n0   = blockIdx.x * BN;     // n fastest: A-panel sharers co-wave
    const int m0   = blockIdx.y * BM;
    const int m_w  = (wid & 1) * 64;      // 2 warps over M
    const int n_w  = (wid >> 1) * 32;     // 8 warps over N

    float C[4][4][4];
    #pragma unroll
    for (int i = 0; i < 4; ++i)
        #pragma unroll
        for (int j = 0; j < 4; ++j)
            #pragma unroll
            for (int q = 0; q < 4; ++q) C[i][j][q] = 0.f;

    // ldmatrix lane address components (layout validated in R4/R5 passes)
    const int a_row = m_w + (lane & 15);
    const int a_cb  = (lane >> 4) * 16;
    const int b_sub = lane >> 3;
    const int b_row = n_w + (lane & 7) + ((b_sub >> 1) << 3);
    const int b_cb  = (b_sub & 1) * 16;

    load_chunk(sb, m0, n0, 0, tid);
    load_chunk(sb + STG_SZ, m0, n0, 1, tid);

    const int NCH = KDIM / BK;            // 64
    for (int kc = 0; kc < NCH; ++kc) {
        if (kc == NCH - 1) asm volatile("cp.async.wait_group 0;" ::: "memory");
        else               asm volatile("cp.async.wait_group 1;" ::: "memory");
        __syncthreads();
        uint32_t stb = sb + (kc % NSTAGE) * STG_SZ;
        if (kc + 2 < NCH)
            load_chunk(sb + ((kc + 2) % NSTAGE) * STG_SZ, m0, n0, kc + 2, tid);

        #pragma unroll
        for (int ks = 0; ks < 2; ++ks) {
            uint32_t A[4][4];
            uint32_t aH = stb + a_row * ROWB + ks * 32 + a_cb;
            #pragma unroll
            for (int mg = 0; mg < 4; ++mg)
                ldsm4(A[mg][0], A[mg][1], A[mg][2], A[mg][3], aH + mg * 16 * ROWB);
            uint32_t bH = stb + SA_SZ + b_row * ROWB + ks * 32 + b_cb;
            #pragma unroll
            for (int g = 0; g < 2; ++g) {
                uint32_t B[4];
                ldsm4(B[0], B[1], B[2], B[3], bH + g * 16 * ROWB);
                #pragma unroll
                for (int mg = 0; mg < 4; ++mg) {
                    mma16816(C[mg][2*g],   A[mg], B[0], B[1]);
                    mma16816(C[mg][2*g+1], A[mg], B[2], B[3]);
                }
            }
        }
    }

    // fused epilogue: out[r, c] = w_input[r, c] * exp[r] / zsum
    float inv = 1.f / g_ZSUM;
    #pragma unroll
    for (int mg = 0; mg < 4; ++mg) {
        int r0 = m0 + m_w + 16 * mg + (lane >> 2);
        float s0 = g_EXP[r0] * inv;
        float s1 = g_EXP[r0 + 8] * inv;
        #pragma unroll
        for (int g8 = 0; g8 < 4; ++g8) {
            int col = n0 + n_w + 8 * g8 + 2 * (lane & 3);
            float2* p0 = (float2*)&out[(size_t)r0 * NDIM + col];
            float2* p1 = (float2*)&out[(size_t)(r0 + 8) * NDIM + col];
            *p0 = make_float2(C[mg][g8][0] * s0, C[mg][g8][1] * s0);
            *p1 = make_float2(C[mg][g8][2] * s1, C[mg][g8][3] * s1);
        }
    }
}

// ---------------- launch ------------------------------------------------------
extern "C" void kernel_launch(void* const* d_in, const int* in_sizes, int n_in,
                              void* d_out, int out_size) {
    // bind inputs by element count (robust to metadata ordering)
    const float* X = nullptr; const float* W = nullptr; const float* a = nullptr;
    for (int i = 0; i < n_in; ++i) {
        if (in_sizes[i] == NTOK * KDIM)      X = (const float*)d_in[i];
        else if (in_sizes[i] == KDIM * NDIM) W = (const float*)d_in[i];
        else if (in_sizes[i] == NDIM)        a = (const float*)d_in[i];
    }
    float* out = (float*)d_out;

    cudaFuncSetAttribute(k_gemm, cudaFuncAttributeMaxDynamicSharedMemorySize,
                         GEMM_SMEM);

    k_init<<<2, 1024>>>();
    k_convX<<<(NTOK * (KDIM / 4)) / 256, 256>>>(X);
    k_convW<<<dim3(KDIM / 32, NDIM / 32), dim3(32, 8)>>>(W);
    k_xsum<<<dim3(KDIM / 256, NTOK / 128), 256>>>(X);
    k_v<<<dim3(NDIM / 256, KDIM / 256), 256>>>(W);
    k_vfin<<<NDIM / 256, 256>>>(a);
    k_u<<<KDIM / 8, 256>>>(W);
    k_scores<<<NTOK / 8, 256>>>(X);
    k_exp<<<NTOK / 256, 256>>>();
    k_gemm<<<dim3(NDIM / BN, NTOK / BM), GTHREADS, GEMM_SMEM>>>(out);
}

// round 8
// speedup vs baseline: 1.9355x; 1.0060x over previous
#include <cuda_runtime.h>
#include <cuda_fp16.h>
#include <cstdint>
#include <cstddef>

#define NTOK 16384
#define KDIM 2048
#define NDIM 1024

// ---------------- static scratch (no runtime allocation) --------------------
__device__ __align__(16) __half g_XH[(size_t)NTOK * KDIM];   // fp16(X)
__device__ __align__(16) __half g_WH[(size_t)NDIM * KDIM];   // fp16(W^T) [n][k]
__device__ float    g_XSUM[KDIM];
__device__ float    g_COLSUM[NDIM];
__device__ float    g_V[NDIM];
__device__ float    g_U[KDIM];
__device__ float    g_SCORES[NTOK];
__device__ float    g_EXP[NTOK];
__device__ unsigned g_SMAXENC;
__device__ float    g_ZSUM;

// ---------------- helpers ----------------------------------------------------
__device__ __forceinline__ uint32_t smem_u32(const void* p) {
    uint32_t r;
    asm("{ .reg .u64 t; cvta.to.shared.u64 t, %1; cvt.u32.u64 %0, t; }"
        : "=r"(r) : "l"(p));
    return r;
}
__device__ __forceinline__ void cp16(uint32_t dst, const void* src) {
    asm volatile("cp.async.cg.shared.global [%0], [%1], 16;"
                 :: "r"(dst), "l"(src) : "memory");
}
__device__ __forceinline__ void ldsm4(uint32_t& r0, uint32_t& r1, uint32_t& r2,
                                      uint32_t& r3, uint32_t addr) {
    asm volatile("ldmatrix.sync.aligned.m8n8.x4.shared.b16 {%0,%1,%2,%3}, [%4];"
                 : "=r"(r0), "=r"(r1), "=r"(r2), "=r"(r3) : "r"(addr));
}
__device__ __forceinline__ void mma16816(float* c, const uint32_t* a,
                                         uint32_t b0, uint32_t b1) {
    asm volatile(
        "mma.sync.aligned.m16n8k16.row.col.f32.f16.f16.f32 "
        "{%0,%1,%2,%3}, {%4,%5,%6,%7}, {%8,%9}, {%0,%1,%2,%3};"
        : "+f"(c[0]), "+f"(c[1]), "+f"(c[2]), "+f"(c[3])
        : "r"(a[0]), "r"(a[1]), "r"(a[2]), "r"(a[3]), "r"(b0), "r"(b1));
}
__device__ __forceinline__ unsigned fenc(float f) {
    unsigned u = __float_as_uint(f);
    return (u & 0x80000000u) ? ~u : (u | 0x80000000u);
}
__device__ __forceinline__ float fdec(unsigned e) {
    unsigned u = (e & 0x80000000u) ? (e & 0x7fffffffu) : ~e;
    return __uint_as_float(u);
}

// ---------------- small kernels ----------------------------------------------
__global__ void k_init() {
    int i = blockIdx.x * 1024 + threadIdx.x;
    if (i < KDIM) g_XSUM[i] = 0.f;
    if (i < NDIM) g_COLSUM[i] = 0.f;
    if (i == 0) { g_SMAXENC = 0x007FFFFFu; g_ZSUM = 0.f; } // enc(-inf)
}

__global__ void k_convX(const float* __restrict__ X) {
    size_t i4 = (size_t)blockIdx.x * blockDim.x + threadIdx.x;
    float4 x = reinterpret_cast<const float4*>(X)[i4];
    __half2* XH2 = reinterpret_cast<__half2*>(g_XH);
    XH2[2*i4]   = __floats2half2_rn(x.x, x.y);
    XH2[2*i4+1] = __floats2half2_rn(x.z, x.w);
}

__global__ void k_convW(const float* __restrict__ W) {
    __shared__ float t[32][33];
    int k0 = blockIdx.x * 32, n0 = blockIdx.y * 32;
    int tx = threadIdx.x, ty = threadIdx.y;       // (32, 8)
    #pragma unroll
    for (int i = ty; i < 32; i += 8)
        t[i][tx] = W[(size_t)(k0 + i) * NDIM + n0 + tx];
    __syncthreads();
    #pragma unroll
    for (int i = ty; i < 32; i += 8)
        g_WH[(size_t)(n0 + i) * KDIM + k0 + tx] = __float2half_rn(t[tx][i]);
}

// xsum[k] = sum_i X[i,k]
__global__ void k_xsum(const float* __restrict__ X) {
    int k = blockIdx.x * 256 + threadIdx.x;
    int r0 = blockIdx.y * 128;
    float a0 = 0.f, a1 = 0.f;
    #pragma unroll 4
    for (int r = 0; r < 128; r += 2) {
        a0 += X[(size_t)(r0 + r) * KDIM + k];
        a1 += X[(size_t)(r0 + r + 1) * KDIM + k];
    }
    atomicAdd(&g_XSUM[k], a0 + a1);
}

// colsum[n] += sum over k-chunk of xsum[k]*W[k][n]
__global__ void k_v(const float* __restrict__ W) {
    int n = blockIdx.x * 256 + threadIdx.x;
    int kb = blockIdx.y * 256;
    float acc = 0.f;
    for (int k = 0; k < 256; ++k)
        acc += g_XSUM[kb + k] * W[(size_t)(kb + k) * NDIM + n];
    atomicAdd(&g_COLSUM[n], acc);
}

__global__ void k_vfin(const float* __restrict__ a) {
    int n = blockIdx.x * 256 + threadIdx.x;
    g_V[n] = a[n] * g_COLSUM[n];
}

// u[k] = sum_n W[k][n]*v[n]
__global__ void k_u(const float* __restrict__ W) {
    __shared__ float sv[NDIM];
    int tid = threadIdx.x, wid = tid >> 5, lid = tid & 31;
    #pragma unroll
    for (int j = 0; j < 4; ++j) sv[tid + 256 * j] = g_V[tid + 256 * j];
    __syncthreads();
    int k = blockIdx.x * 8 + wid;
    float acc = 0.f;
    #pragma unroll 8
    for (int j = 0; j < 32; ++j)
        acc += W[(size_t)k * NDIM + lid + 32 * j] * sv[lid + 32 * j];
    #pragma unroll
    for (int o = 16; o > 0; o >>= 1) acc += __shfl_xor_sync(0xffffffff, acc, o);
    if (lid == 0) g_U[k] = acc;
}

// scores[i] = X[i,:] . u ; track max via encoded atomicMax
__global__ void k_scores(const float* __restrict__ X) {
    __shared__ float su[KDIM];
    int tid = threadIdx.x, wid = tid >> 5, lid = tid & 31;
    #pragma unroll
    for (int j = 0; j < 8; ++j) su[tid + 256 * j] = g_U[tid + 256 * j];
    __syncthreads();
    int i = blockIdx.x * 8 + wid;
    const float* xr = X + (size_t)i * KDIM;
    float acc = 0.f;
    #pragma unroll 8
    for (int j = 0; j < 64; ++j)
        acc += xr[lid + 32 * j] * su[lid + 32 * j];
    #pragma unroll
    for (int o = 16; o > 0; o >>= 1) acc += __shfl_xor_sync(0xffffffff, acc, o);
    if (lid == 0) {
        g_SCORES[i] = acc;
        atomicMax(&g_SMAXENC, fenc(acc));
    }
}

__global__ void k_exp() {
    __shared__ float red[256];
    int i = blockIdx.x * 256 + threadIdx.x;
    float smax = fdec(g_SMAXENC);
    float e = expf(g_SCORES[i] - smax);
    g_EXP[i] = e;
    red[threadIdx.x] = e;
    __syncthreads();
    for (int o = 128; o > 0; o >>= 1) {
        if (threadIdx.x < o) red[threadIdx.x] += red[threadIdx.x + o];
        __syncthreads();
    }
    if (threadIdx.x == 0) atomicAdd(&g_ZSUM, red[0]);
}

// ---------------- GEMM: out = (X @ W) * attn  via mma.sync fp16 --------------
// BM=128, BN=256, BK=32; 512 threads (16 warps, 2x8, 64x32 warp tile);
// 3-stage cp.async pipeline; 80B padded smem rows (conflict-free ldmatrix);
// fused softmax-scaled epilogue. Single fp16 pass (fp32 accumulate).
#define BM 128
#define BN 256
#define BK 32
#define ROWB 80
#define SA_SZ (BM * ROWB)                // 10240
#define SB_SZ (BN * ROWB)                // 20480
#define STG_SZ (SA_SZ + SB_SZ)           // 30720
#define NSTAGE 3
#define GEMM_SMEM (NSTAGE * STG_SZ)      // 92160
#define GTHREADS 512

__device__ __forceinline__ void load_chunk(uint32_t stb, int m0, int n0, int kc, int tid) {
    const size_t rowb = KDIM * 2;
    size_t ck = (size_t)kc * 64;          // 32 fp16 = 64 bytes along K
    // A: 128 rows x 4 x 16B = 512 slots
    {
        int row = tid >> 2, c = tid & 3;
        const char* src = (const char*)g_XH + (size_t)(m0 + row) * rowb + ck + c * 16;
        cp16(stb + row * ROWB + c * 16, src);
    }
    // B: 256 rows x 4 x 16B = 1024 slots
    #pragma unroll
    for (int it = 0; it < 2; ++it) {
        int idx = tid + it * GTHREADS;
        int row = idx >> 2, c = idx & 3;
        const char* src = (const char*)g_WH + (size_t)(n0 + row) * rowb + ck + c * 16;
        cp16(stb + SA_SZ + row * ROWB + c * 16, src);
    }
    asm volatile("cp.async.commit_group;" ::: "memory");
}

__global__ void __launch_bounds__(GTHREADS, 1) k_gemm(float* __restrict__ out) {
    extern __shared__ char smem[];
    uint32_t sb = smem_u32(smem);
    const int tid  = threadIdx.x;
    const int wid  = tid >> 5, lane = tid & 31;
    const int n0   = blockIdx.x * BN;     // n fastest: A-panel sharers co-wave
    const int m0   = blockIdx.y * BM;
    const int m_w  = (wid & 1) * 64;      // 2 warps over M
    const int n_w  = (wid >> 1) * 32;     // 8 warps over N

    float C[4][4][4];
    #pragma unroll
    for (int i = 0; i < 4; ++i)
        #pragma unroll
        for (int j = 0; j < 4; ++j)
            #pragma unroll
            for (int q = 0; q < 4; ++q) C[i][j][q] = 0.f;

    // ldmatrix lane address components (layout validated in R4/R5 passes)
    const int a_row = m_w + (lane & 15);
    const int a_cb  = (lane >> 4) * 16;
    const int b_sub = lane >> 3;
    const int b_row = n_w + (lane & 7) + ((b_sub >> 1) << 3);
    const int b_cb  = (b_sub & 1) * 16;

    load_chunk(sb, m0, n0, 0, tid);
    load_chunk(sb + STG_SZ, m0, n0, 1, tid);

    const int NCH = KDIM / BK;            // 64
    for (int kc = 0; kc < NCH; ++kc) {
        if (kc == NCH - 1) asm volatile("cp.async.wait_group 0;" ::: "memory");
        else               asm volatile("cp.async.wait_group 1;" ::: "memory");
        __syncthreads();
        uint32_t stb = sb + (kc % NSTAGE) * STG_SZ;
        if (kc + 2 < NCH)
            load_chunk(sb + ((kc + 2) % NSTAGE) * STG_SZ, m0, n0, kc + 2, tid);

        #pragma unroll
        for (int ks = 0; ks < 2; ++ks) {
            uint32_t A[4][4];
            uint32_t aH = stb + a_row * ROWB + ks * 32 + a_cb;
            #pragma unroll
            for (int mg = 0; mg < 4; ++mg)
                ldsm4(A[mg][0], A[mg][1], A[mg][2], A[mg][3], aH + mg * 16 * ROWB);
            uint32_t bH = stb + SA_SZ + b_row * ROWB + ks * 32 + b_cb;
            #pragma unroll
            for (int g = 0; g < 2; ++g) {
                uint32_t B[4];
                ldsm4(B[0], B[1], B[2], B[3], bH + g * 16 * ROWB);
                #pragma unroll
                for (int mg = 0; mg < 4; ++mg) {
                    mma16816(C[mg][2*g],   A[mg], B[0], B[1]);
                    mma16816(C[mg][2*g+1], A[mg], B[2], B[3]);
                }
            }
        }
    }

    // fused epilogue: out[r, c] = w_input[r, c] * exp[r] / zsum
    float inv = 1.f / g_ZSUM;
    #pragma unroll
    for (int mg = 0; mg < 4; ++mg) {
        int r0 = m0 + m_w + 16 * mg + (lane >> 2);
        float s0 = g_EXP[r0] * inv;
        float s1 = g_EXP[r0 + 8] * inv;
        #pragma unroll
        for (int g8 = 0; g8 < 4; ++g8) {
            int col = n0 + n_w + 8 * g8 + 2 * (lane & 3);
            float2* p0 = (float2*)&out[(size_t)r0 * NDIM + col];
            float2* p1 = (float2*)&out[(size_t)(r0 + 8) * NDIM + col];
            *p0 = make_float2(C[mg][g8][0] * s0, C[mg][g8][1] * s0);
            *p1 = make_float2(C[mg][g8][2] * s1, C[mg][g8][3] * s1);
        }
    }
}

// ---------------- launch ------------------------------------------------------
extern "C" void kernel_launch(void* const* d_in, const int* in_sizes, int n_in,
                              void* d_out, int out_size) {
    // bind inputs by element count (robust to metadata ordering)
    const float* X = nullptr; const float* W = nullptr; const float* a = nullptr;
    for (int i = 0; i < n_in; ++i) {
        if (in_sizes[i] == NTOK * KDIM)      X = (const float*)d_in[i];
        else if (in_sizes[i] == KDIM * NDIM) W = (const float*)d_in[i];
        else if (in_sizes[i] == NDIM)        a = (const float*)d_in[i];
    }
    float* out = (float*)d_out;

    cudaFuncSetAttribute(k_gemm, cudaFuncAttributeMaxDynamicSharedMemorySize,
                         GEMM_SMEM);

    k_init<<<2, 1024>>>();
    k_convX<<<(NTOK * (KDIM / 4)) / 256, 256>>>(X);
    k_convW<<<dim3(KDIM / 32, NDIM / 32), dim3(32, 8)>>>(W);
    k_xsum<<<dim3(KDIM / 256, NTOK / 128), 256>>>(X);
    k_v<<<dim3(NDIM / 256, KDIM / 256), 256>>>(W);
    k_vfin<<<NDIM / 256, 256>>>(a);
    k_u<<<KDIM / 8, 256>>>(W);
    k_scores<<<NTOK / 8, 256>>>(X);
    k_exp<<<NTOK / 256, 256>>>();
    k_gemm<<<dim3(NDIM / BN, NTOK / BM), GTHREADS, GEMM_SMEM>>>(out);
}